// round 6
// baseline (speedup 1.0000x reference)
#include <cuda_runtime.h>
#include <cuda_bf16.h>
#include <cstdint>

#define D_DIM 1024
#define L_IN  1024
#define B_SZ  32
#define L_OUT 511
#define M_TOT (B_SZ * L_OUT)
#define K_CB  2048
#define K_C1  4096
#define BN_EPS 1e-5f
#define Q_ELEMS (B_SZ * D_DIM * L_OUT)

#define STAGE_B   36864   /* (128*72)*2B per tile, A+B */
#define TILE_A_B  18432
#define SMEM_GEMM (3 * STAGE_B + 1024)

/* ---------------- scratch ---------------- */
__device__ float g_h [M_TOT * D_DIM];
__device__ float g_h2[M_TOT * D_DIM];
__device__ float g_part[2 * 64 * D_DIM];
__device__ float g_scale1[D_DIM], g_shift1[D_DIM];
__device__ float g_scale2[D_DIM], g_shift2[D_DIM];
__device__ float g_e2[K_CB];
__device__ unsigned long long g_keys[M_TOT];
__device__ double g_loss;

__device__ __align__(128) __nv_bfloat16 g_Axs[3][B_SZ * D_DIM * L_IN];
__device__ __align__(128) __nv_bfloat16 g_A2s[3][M_TOT * D_DIM];
__device__ __align__(128) __nv_bfloat16 g_A3s[3][M_TOT * D_DIM];
__device__ __align__(128) __nv_bfloat16 g_W1s[3][D_DIM * K_C1];
__device__ __align__(128) __nv_bfloat16 g_W2s[3][D_DIM * D_DIM];
__device__ __align__(128) __nv_bfloat16 g_CBs[3][K_CB * D_DIM];

/* ---------------- asm helpers ---------------- */
__device__ __forceinline__ uint32_t s2u(const void* p) {
    uint32_t a;
    asm("{ .reg .u64 t; cvta.to.shared.u64 t, %1; cvt.u32.u64 %0, t; }" : "=r"(a) : "l"(p));
    return a;
}
#define CP16(dst, src) asm volatile("cp.async.cg.shared.global [%0],[%1],16;" :: "r"(dst), "l"(src))
#define CP4(dst, src)  asm volatile("cp.async.ca.shared.global [%0],[%1],4;"  :: "r"(dst), "l"(src))
#define CPCOMMIT()     asm volatile("cp.async.commit_group;" ::: "memory")
#define CPWAIT1()      asm volatile("cp.async.wait_group 1;" ::: "memory")
#define LDSM4(r, a) \
    asm volatile("ldmatrix.sync.aligned.m8n8.x4.shared.b16 {%0,%1,%2,%3}, [%4];" \
        : "=r"((r)[0]), "=r"((r)[1]), "=r"((r)[2]), "=r"((r)[3]) : "r"(a))
#define MMA16(c, a, b0, b1) \
    asm volatile("mma.sync.aligned.m16n8k16.row.col.f32.bf16.bf16.f32 " \
        "{%0,%1,%2,%3},{%4,%5,%6,%7},{%8,%9},{%0,%1,%2,%3};" \
        : "+f"((c)[0]), "+f"((c)[1]), "+f"((c)[2]), "+f"((c)[3]) \
        : "r"((a)[0]), "r"((a)[1]), "r"((a)[2]), "r"((a)[3]), "r"(b0), "r"(b1))

__device__ __forceinline__ void split3(float x, unsigned short& o0, unsigned short& o1, unsigned short& o2) {
    __nv_bfloat16 b0 = __float2bfloat16(x);
    float r1 = x - __bfloat162float(b0);
    __nv_bfloat16 b1 = __float2bfloat16(r1);
    float r2 = r1 - __bfloat162float(b1);
    __nv_bfloat16 b2 = __float2bfloat16(r2);
    o0 = *(unsigned short*)&b0; o1 = *(unsigned short*)&b1; o2 = *(unsigned short*)&b2;
}
__device__ __forceinline__ unsigned long long packkey(float s, int k) {
    unsigned u = __float_as_uint(s);
    u = (u & 0x80000000u) ? ~u : (u | 0x80000000u);
    return ((unsigned long long)u << 32) | (unsigned)k;
}

/* ---------------- small kernels ---------------- */
__global__ void init_kernel() {
    int i = blockIdx.x * blockDim.x + threadIdx.x;
    if (i < M_TOT) g_keys[i] = 0xFFFFFFFFFFFFFFFFULL;
    if (i == 0) g_loss = 0.0;
}

__global__ void split_w(const float* __restrict__ in, int n, int which) {
    int i = blockIdx.x * 256 + threadIdx.x;
    if (i >= n) return;
    __nv_bfloat16 *o0, *o1, *o2;
    if (which == 0)      { o0 = g_W1s[0]; o1 = g_W1s[1]; o2 = g_W1s[2]; }
    else if (which == 1) { o0 = g_W2s[0]; o1 = g_W2s[1]; o2 = g_W2s[2]; }
    else                 { o0 = g_CBs[0]; o1 = g_CBs[1]; o2 = g_CBs[2]; }
    unsigned short h0, h1, h2;
    split3(in[i], h0, h1, h2);
    o0[i] = *(__nv_bfloat16*)&h0; o1[i] = *(__nv_bfloat16*)&h1; o2[i] = *(__nv_bfloat16*)&h2;
}

__global__ void split_x(const float* __restrict__ x) {
    int i = blockIdx.x * 256 + threadIdx.x;
    if (i >= B_SZ * D_DIM * L_IN) return;
    unsigned short h0, h1, h2;
    split3(x[i], h0, h1, h2);
    g_Axs[0][i] = *(__nv_bfloat16*)&h0;
    g_Axs[1][i] = *(__nv_bfloat16*)&h1;
    g_Axs[2][i] = *(__nv_bfloat16*)&h2;
}

__global__ void bn_split(int which) {   /* 0: relu(bn1(g_h))->A2s ; 1: bn2(g_h2)->A3s */
    int i = blockIdx.x * 256 + threadIdx.x;
    if (i >= M_TOT * D_DIM) return;
    int d = i & (D_DIM - 1);
    float v;
    if (which == 0) {
        v = g_h[i] * g_scale1[d] + g_shift1[d];
        v = fmaxf(v, 0.f);
    } else {
        v = g_h2[i] * g_scale2[d] + g_shift2[d];
    }
    unsigned short h0, h1, h2;
    split3(v, h0, h1, h2);
    if (which == 0) {
        g_A2s[0][i] = *(__nv_bfloat16*)&h0; g_A2s[1][i] = *(__nv_bfloat16*)&h1; g_A2s[2][i] = *(__nv_bfloat16*)&h2;
    } else {
        g_A3s[0][i] = *(__nv_bfloat16*)&h0; g_A3s[1][i] = *(__nv_bfloat16*)&h1; g_A3s[2][i] = *(__nv_bfloat16*)&h2;
    }
}

__global__ void bn_stage1(int which) {
    const float* h = which ? g_h2 : g_h;
    int d = blockIdx.y * 128 + threadIdx.x;
    int s = blockIdx.x;
    float sum = 0.f, sq = 0.f;
    int m0 = s * 256, m1 = m0 + 256; if (m1 > M_TOT) m1 = M_TOT;
    for (int m = m0; m < m1; m++) {
        float v = h[(size_t)m * D_DIM + d];
        sum += v; sq += v * v;
    }
    g_part[s * D_DIM + d] = sum;
    g_part[64 * D_DIM + s * D_DIM + d] = sq;
}

__global__ void bn_stage2(const float* __restrict__ gam, const float* __restrict__ bet, int which) {
    int d = blockIdx.x * 256 + threadIdx.x;
    float sum = 0.f, sq = 0.f;
    for (int s = 0; s < 64; s++) {
        sum += g_part[s * D_DIM + d];
        sq  += g_part[64 * D_DIM + s * D_DIM + d];
    }
    float mean = sum / (float)M_TOT;
    float var  = sq / (float)M_TOT - mean * mean;
    float sc = gam[d] * rsqrtf(var + BN_EPS);
    float sh = bet[d] - mean * sc;
    if (which == 0) { g_scale1[d] = sc; g_shift1[d] = sh; }
    else            { g_scale2[d] = sc; g_shift2[d] = sh; }
}

__global__ void e2_kernel(const float* __restrict__ cb) {
    int k = blockIdx.x;
    float s = 0.f;
    for (int d = threadIdx.x; d < D_DIM; d += 128) {
        float v = cb[(size_t)k * D_DIM + d];
        s += v * v;
    }
    __shared__ float red[128];
    red[threadIdx.x] = s; __syncthreads();
    for (int off = 64; off; off >>= 1) {
        if (threadIdx.x < off) red[threadIdx.x] += red[threadIdx.x + off];
        __syncthreads();
    }
    if (threadIdx.x == 0) g_e2[k] = red[0];
}

/* ---------------- HMMA split-bf16 GEMM ----------------
 * C[m][n] = sum_pairs A_pa[m][k] * B_pb[n][k]
 * mode 0: A = im2col(x splits) K=4096, B = W1s, out g_h + b1
 * mode 1: A = A2s K=1024, B = W2s, out g_h2 = g_h + . + b2
 * mode 2: A = A3s K=1024, B = CBs, epilogue argmin(e2 - 2*dot)
 */
__global__ void __launch_bounds__(256)
gemm_kernel(int mode, const float* __restrict__ aux_in, int Kdim) {
    extern __shared__ __align__(16) char sm[];
    uint32_t sb = s2u(sm);
    int tid = threadIdx.x;
    int l = tid & 31, wid = tid >> 5;
    int n0 = blockIdx.x * 128, m0 = blockIdx.y * 128;

    int*   rowbase = (int*)(sm + 3 * STAGE_B);
    float* auxs    = (float*)(sm + 3 * STAGE_B + 512);

    const __nv_bfloat16 *Aps[3], *Bps[3];
    if (mode == 0) {
        Aps[0] = g_Axs[0]; Aps[1] = g_Axs[1]; Aps[2] = g_Axs[2];
        Bps[0] = g_W1s[0]; Bps[1] = g_W1s[1]; Bps[2] = g_W1s[2];
    } else if (mode == 1) {
        Aps[0] = g_A2s[0]; Aps[1] = g_A2s[1]; Aps[2] = g_A2s[2];
        Bps[0] = g_W2s[0]; Bps[1] = g_W2s[1]; Bps[2] = g_W2s[2];
    } else {
        Aps[0] = g_A3s[0]; Aps[1] = g_A3s[1]; Aps[2] = g_A3s[2];
        Bps[0] = g_CBs[0]; Bps[1] = g_CBs[1]; Bps[2] = g_CBs[2];
    }
    const float* aux = (mode == 2) ? g_e2 : aux_in;

    if (tid < 128) {
        int m = m0 + tid; if (m >= M_TOT) m = M_TOT - 1;
        if (mode == 0) { int b = m / L_OUT; int lq = m - b * L_OUT; rowbase[tid] = b * (D_DIM * L_IN) + 2 * lq; }
        else rowbase[tid] = m * D_DIM;
        auxs[tid] = aux[n0 + tid];
    }
    __syncthreads();

    const int pa[6] = {0, 0, 1, 1, 0, 2};
    const int pb[6] = {0, 1, 0, 1, 2, 0};
    int kchunks = Kdim >> 6;
    int total = 6 * kchunks;

    /* tile loader */
    auto load_tile = [&](int stage, int t) {
        int pair = t / kchunks, kc = t - pair * kchunks;
        const __nv_bfloat16* Ac = Aps[pa[pair]];
        const __nv_bfloat16* Bc = Bps[pb[pair]];
        uint32_t Ab = sb + stage * STAGE_B;
        uint32_t Bb = Ab + TILE_A_B;
        if (mode == 0) {
#pragma unroll
            for (int i = 0; i < 16; i++) {
                int idx = tid + i * 256;
                int r = idx >> 5, s = idx & 31;
                const __nv_bfloat16* src = Ac + rowbase[r] + (kc * 16 + (s >> 1)) * 1024 + (s & 1) * 2;
                CP4(Ab + r * 144 + s * 4, src);
            }
        } else {
#pragma unroll
            for (int i = 0; i < 4; i++) {
                int idx = tid + i * 256;
                int r = idx >> 3, s = idx & 7;
                const __nv_bfloat16* src = Ac + (size_t)rowbase[r] + kc * 64 + s * 8;
                CP16(Ab + r * 144 + s * 16, src);
            }
        }
#pragma unroll
        for (int i = 0; i < 4; i++) {
            int idx = tid + i * 256;
            int r = idx >> 3, s = idx & 7;
            const __nv_bfloat16* src = Bc + (size_t)(n0 + r) * Kdim + kc * 64 + s * 8;
            CP16(Bb + r * 144 + s * 16, src);
        }
        CPCOMMIT();
    };

    load_tile(0, 0);
    load_tile(1, 1);

    float acc[2][8][4];
#pragma unroll
    for (int i = 0; i < 2; i++)
#pragma unroll
        for (int j = 0; j < 8; j++)
#pragma unroll
            for (int q = 0; q < 4; q++) acc[i][j][q] = 0.f;

    uint32_t rA = (uint32_t)(((wid & 3) * 32 + (l & 15)) * 144 + (l >> 4) * 16);
    uint32_t rB = (uint32_t)(((wid >> 2) * 64 + ((l >> 4) & 1) * 8 + (l & 7)) * 144 + ((l >> 3) & 1) * 16);

    for (int t = 0; t < total; t++) {
        CPWAIT1();
        __syncthreads();
        if (t + 2 < total) load_tile((t + 2) % 3, t + 2);
        uint32_t Ab = sb + (t % 3) * STAGE_B;
        uint32_t Bb = Ab + TILE_A_B;
#pragma unroll
        for (int ks = 0; ks < 4; ks++) {
            uint32_t a0[4], a1[4], bf[4][4];
            LDSM4(a0, Ab + rA + ks * 32);
            LDSM4(a1, Ab + rA + 2304 + ks * 32);
#pragma unroll
            for (int g = 0; g < 4; g++) LDSM4(bf[g], Bb + rB + g * 2304 + ks * 32);
#pragma unroll
            for (int g = 0; g < 4; g++) {
                MMA16(acc[0][2 * g],     a0, bf[g][0], bf[g][1]);
                MMA16(acc[0][2 * g + 1], a0, bf[g][2], bf[g][3]);
                MMA16(acc[1][2 * g],     a1, bf[g][0], bf[g][1]);
                MMA16(acc[1][2 * g + 1], a1, bf[g][2], bf[g][3]);
            }
        }
    }

    /* epilogue */
    int wm = (wid & 3) * 32, wn = (wid >> 2) * 64;
    if (mode == 2) {
#pragma unroll
        for (int mi = 0; mi < 2; mi++) {
#pragma unroll
            for (int h = 0; h < 2; h++) {
                int m = m0 + wm + mi * 16 + h * 8 + (l >> 2);
                float best = 3.4e38f; int bk = 0;
#pragma unroll
                for (int nj = 0; nj < 8; nj++) {
#pragma unroll
                    for (int c = 0; c < 2; c++) {
                        int lc = wn + nj * 8 + (l & 3) * 2 + c;
                        float scv = auxs[lc] - 2.f * acc[mi][nj][h * 2 + c];
                        if (scv < best) { best = scv; bk = n0 + lc; }
                    }
                }
                unsigned long long key = packkey(best, bk);
                unsigned long long o1 = __shfl_xor_sync(0xFFFFFFFFu, key, 1);
                if (o1 < key) key = o1;
                unsigned long long o2 = __shfl_xor_sync(0xFFFFFFFFu, key, 2);
                if (o2 < key) key = o2;
                if ((l & 3) == 0 && m < M_TOT) atomicMin(&g_keys[m], key);
            }
        }
    } else {
        float* dst = (mode == 0) ? g_h : g_h2;
#pragma unroll
        for (int mi = 0; mi < 2; mi++) {
#pragma unroll
            for (int h = 0; h < 2; h++) {
                int m = m0 + wm + mi * 16 + h * 8 + (l >> 2);
                if (m >= M_TOT) continue;
#pragma unroll
                for (int nj = 0; nj < 8; nj++) {
                    int lc = wn + nj * 8 + (l & 3) * 2;
                    size_t off = (size_t)m * D_DIM + n0 + lc;
                    float2 v;
                    v.x = acc[mi][nj][h * 2]     + auxs[lc];
                    v.y = acc[mi][nj][h * 2 + 1] + auxs[lc + 1];
                    if (mode == 1) {
                        float2 rr = *(const float2*)(g_h + off);
                        v.x += rr.x; v.y += rr.y;
                    }
                    *(float2*)(dst + off) = v;
                }
            }
        }
    }
}

/* ---------------- gather + loss ---------------- */
__global__ void gather_kernel(const float* __restrict__ cb, float* __restrict__ out) {
    int b = blockIdx.y;
    int l = blockIdx.x * 32 + threadIdx.x;
    int dt = threadIdx.y;
    float local = 0.f;
    if (l < L_OUT) {
        int m = b * L_OUT + l;
        int id = (int)(unsigned)(g_keys[m] & 0xFFFFFFFFULL);
        if (dt == 0) out[Q_ELEMS + m] = (float)id;
        for (int d = dt; d < D_DIM; d += 8) {
            float q = cb[(size_t)id * D_DIM + d];
            float z = g_h2[(size_t)m * D_DIM + d] * g_scale2[d] + g_shift2[d];
            out[(size_t)b * (D_DIM * L_OUT) + (size_t)d * L_OUT + l] = q;
            float diff = z - q;
            local += diff * diff;
        }
    }
    __shared__ double red[256];
    int t = threadIdx.y * 32 + threadIdx.x;
    red[t] = (double)local;
    __syncthreads();
    for (int off = 128; off; off >>= 1) {
        if (t < off) red[t] += red[t + off];
        __syncthreads();
    }
    if (t == 0) atomicAdd(&g_loss, red[0]);
}

__global__ void finalize_kernel(float* __restrict__ out) {
    if (threadIdx.x == 0 && blockIdx.x == 0) {
        float loss = (float)(g_loss / (double)Q_ELEMS);
        out[Q_ELEMS + M_TOT]     = loss;
        out[Q_ELEMS + M_TOT + 1] = loss;
    }
}

/* ---------------- launch ---------------- */
extern "C" void kernel_launch(void* const* d_in, const int* in_sizes, int n_in,
                              void* d_out, int out_size) {
    const float* x   = (const float*)d_in[0];
    const float* w1  = (const float*)d_in[1];
    const float* b1  = (const float*)d_in[2];
    const float* g1  = (const float*)d_in[3];
    const float* be1 = (const float*)d_in[4];
    const float* w2  = (const float*)d_in[5];
    const float* b2  = (const float*)d_in[6];
    const float* g2  = (const float*)d_in[7];
    const float* be2 = (const float*)d_in[8];
    const float* cb  = (const float*)d_in[9];
    float* out = (float*)d_out;

    static bool attr_set = false;
    if (!attr_set) {
        cudaFuncSetAttribute(gemm_kernel, cudaFuncAttributeMaxDynamicSharedMemorySize, SMEM_GEMM);
        attr_set = true;
    }

    init_kernel<<<64, 256>>>();
    split_w<<<(D_DIM * K_C1 + 255) / 256, 256>>>(w1, D_DIM * K_C1, 0);
    split_w<<<(D_DIM * D_DIM + 255) / 256, 256>>>(w2, D_DIM * D_DIM, 1);
    split_w<<<(K_CB * D_DIM + 255) / 256, 256>>>(cb, K_CB * D_DIM, 2);
    split_x<<<(B_SZ * D_DIM * L_IN + 255) / 256, 256>>>(x);

    gemm_kernel<<<dim3(8, 128), 256, SMEM_GEMM>>>(0, b1, K_C1);
    bn_stage1<<<dim3(64, 8), 128>>>(0);
    bn_stage2<<<4, 256>>>(g1, be1, 0);
    bn_split<<<(M_TOT * D_DIM + 255) / 256, 256>>>(0);

    gemm_kernel<<<dim3(8, 128), 256, SMEM_GEMM>>>(1, b2, D_DIM);
    bn_stage1<<<dim3(64, 8), 128>>>(1);
    bn_stage2<<<4, 256>>>(g2, be2, 1);
    bn_split<<<(M_TOT * D_DIM + 255) / 256, 256>>>(1);

    e2_kernel<<<K_CB, 128>>>(cb);
    gemm_kernel<<<dim3(16, 128), 256, SMEM_GEMM>>>(2, nullptr, D_DIM);

    gather_kernel<<<dim3(16, B_SZ), dim3(32, 8)>>>(cb, out);
    finalize_kernel<<<1, 32>>>(out);
}

// round 7
// speedup vs baseline: 3.2801x; 3.2801x over previous
#include <cuda_runtime.h>
#include <cuda_fp16.h>
#include <cstdint>

#define D_DIM 1024
#define L_IN  1024
#define B_SZ  32
#define L_OUT 511
#define M_TOT (B_SZ * L_OUT)
#define K_CB  2048
#define K_C1  4096
#define BN_EPS 1e-5f
#define Q_ELEMS (B_SZ * D_DIM * L_OUT)

/* GEMM geometry: CTA tile 256m x 128n, k-chunk 64.
 * Packed A block  (per m-tile,kchunk): comp0 32KB + comp1 32KB = 64KB (pre-swizzled)
 * Packed B block  (per n-tile,kchunk): comp0 16KB + comp1 16KB = 32KB
 */
#define STAGE_B 98304
#define SMEM_GEMM (1024 + 2 * STAGE_B)

/* ---------------- scratch ---------------- */
__device__ float g_h [M_TOT * D_DIM];
__device__ float g_h2[M_TOT * D_DIM];
__device__ float g_part[2 * 64 * D_DIM];
__device__ float g_scale1[D_DIM], g_shift1[D_DIM];
__device__ float g_scale2[D_DIM], g_shift2[D_DIM];
__device__ float g_e2[K_CB];
__device__ unsigned long long g_keys[M_TOT];
__device__ double g_loss;

__device__ __align__(128) __half g_Ax [64ULL * 64 * 32768];  /* im2col x, 64 mtiles x 64 kc */
__device__ __align__(128) __half g_A2p[64ULL * 16 * 32768];
__device__ __align__(128) __half g_A3p[64ULL * 16 * 32768];
__device__ __align__(128) __half g_W1p[8ULL  * 64 * 16384];
__device__ __align__(128) __half g_W2p[8ULL  * 16 * 16384];
__device__ __align__(128) __half g_CBp[16ULL * 16 * 16384];

/* ---------------- asm helpers ---------------- */
__device__ __forceinline__ uint32_t s2u(const void* p) {
    uint32_t a;
    asm("{ .reg .u64 t; cvta.to.shared.u64 t, %1; cvt.u32.u64 %0, t; }" : "=r"(a) : "l"(p));
    return a;
}
#define MBAR_INIT(m, c) asm volatile("mbarrier.init.shared.b64 [%0], %1;" :: "r"(m), "r"(c) : "memory")
#define EXPECT_TX(m, b) asm volatile("mbarrier.arrive.expect_tx.shared.b64 _, [%0], %1;" :: "r"(m), "r"(b) : "memory")
#define BULK_G2S(dst, src, bytes, mb) \
    asm volatile("cp.async.bulk.shared::cluster.global.mbarrier::complete_tx::bytes [%0], [%1], %2, [%3];" \
        :: "r"(dst), "l"(src), "r"(bytes), "r"(mb) : "memory")
#define MBAR_WAIT(m, ph) do { \
    asm volatile("{\n\t.reg .pred P;\n\tW%=:\n\t" \
        "mbarrier.try_wait.parity.shared.b64 P, [%0], %1;\n\t" \
        "@P bra.uni D%=;\n\tbra.uni W%=;\n\tD%=:\n\t}" :: "r"(m), "r"(ph) : "memory"); \
} while (0)
#define LDSM4(r, a) \
    asm volatile("ldmatrix.sync.aligned.m8n8.x4.shared.b16 {%0,%1,%2,%3}, [%4];" \
        : "=r"((r)[0]), "=r"((r)[1]), "=r"((r)[2]), "=r"((r)[3]) : "r"(a))
#define MMA16(c, a, b0, b1) \
    asm volatile("mma.sync.aligned.m16n8k16.row.col.f32.f16.f16.f32 " \
        "{%0,%1,%2,%3},{%4,%5,%6,%7},{%8,%9},{%0,%1,%2,%3};" \
        : "+f"((c)[0]), "+f"((c)[1]), "+f"((c)[2]), "+f"((c)[3]) \
        : "r"((a)[0]), "r"((a)[1]), "r"((a)[2]), "r"((a)[3]), "r"(b0), "r"(b1))

__device__ __forceinline__ void split2(float x, __half& h0, __half& h1) {
    h0 = __float2half_rn(x);
    h1 = __float2half_rn(x - __half2float(h0));
}
__device__ __forceinline__ unsigned long long packkey(float s, int k) {
    unsigned u = __float_as_uint(s);
    u = (u & 0x80000000u) ? ~u : (u | 0x80000000u);
    return ((unsigned long long)u << 32) | (unsigned)k;
}

/* ---------------- small kernels ---------------- */
__global__ void init_kernel() {
    int i = blockIdx.x * blockDim.x + threadIdx.x;
    if (i < M_TOT) g_keys[i] = 0xFFFFFFFFFFFFFFFFULL;
    if (i == 0) g_loss = 0.0;
}

/* pack fp32 [N x K] weights -> tile-major, swizzled fp16x2 blocks */
__global__ void pack_w(const float* __restrict__ w, int K, __half* __restrict__ out, int total) {
    int id = blockIdx.x * 256 + threadIdx.x;
    if (id >= total) return;
    int kunits = K >> 3;
    int n = id / kunits;
    int kp = (id - n * kunits) << 3;
    int nt = n >> 7, rr = n & 127, kc = kp >> 6, c = (kp & 63) >> 3;
    float4 f0 = *(const float4*)(w + (size_t)n * K + kp);
    float4 f1 = *(const float4*)(w + (size_t)n * K + kp + 4);
    float v[8] = {f0.x, f0.y, f0.z, f0.w, f1.x, f1.y, f1.z, f1.w};
    __half t0[8], t1[8];
#pragma unroll
    for (int j = 0; j < 8; j++) split2(v[j], t0[j], t1[j]);
    size_t blk = ((size_t)nt * (K >> 6) + kc) * 16384;
    int off = rr * 64 + ((c * 8) ^ ((rr & 7) << 3));
    *(uint4*)&out[blk + off]        = *(uint4*)t0;
    *(uint4*)&out[blk + 8192 + off] = *(uint4*)t1;
}

/* pack im2col(x) -> g_Ax */
__global__ void pack_x(const float* __restrict__ x) {
    int id = blockIdx.x * 256 + threadIdx.x;   /* < 64*64*2048 = 8388608 */
    if (id >= 64 * 64 * 2048) return;
    int mt = id >> 17;
    int rem = id & 131071;
    int kc = rem >> 11;
    int rr = (rem >> 3) & 255;
    int c  = rem & 7;
    int m = mt * 256 + rr; if (m >= M_TOT) m = M_TOT - 1;
    int b = m / L_OUT, l = m - b * L_OUT;
    int i0 = kc * 16 + c * 2;
    const float* p0 = x + (size_t)b * (D_DIM * L_IN) + (size_t)i0 * L_IN + 2 * l;
    float v[8];
    float2 q;
    q = *(const float2*)(p0);          v[0] = q.x; v[1] = q.y;
    q = *(const float2*)(p0 + 2);      v[2] = q.x; v[3] = q.y;
    q = *(const float2*)(p0 + 1024);   v[4] = q.x; v[5] = q.y;
    q = *(const float2*)(p0 + 1026);   v[6] = q.x; v[7] = q.y;
    __half t0[8], t1[8];
#pragma unroll
    for (int j = 0; j < 8; j++) split2(v[j], t0[j], t1[j]);
    size_t blk = ((size_t)(mt * 64 + kc)) * 32768;
    int off = rr * 64 + ((c * 8) ^ ((rr & 7) << 3));
    *(uint4*)&g_Ax[blk + off]         = *(uint4*)t0;
    *(uint4*)&g_Ax[blk + 16384 + off] = *(uint4*)t1;
}

/* BN transform + split + pack activations */
__global__ void pack_bn(int which) {
    int id = blockIdx.x * 256 + threadIdx.x;   /* < 64*16*2048 = 2097152 */
    if (id >= 64 * 16 * 2048) return;
    int mt = id >> 15;
    int rem = id & 32767;
    int kc = rem >> 11;
    int rr = (rem >> 3) & 255;
    int c  = rem & 7;
    int m = mt * 256 + rr; if (m >= M_TOT) m = M_TOT - 1;
    int d0 = kc * 64 + c * 8;
    const float* src = which ? g_h2 : g_h;
    float4 f0 = *(const float4*)(src + (size_t)m * D_DIM + d0);
    float4 f1 = *(const float4*)(src + (size_t)m * D_DIM + d0 + 4);
    float v[8] = {f0.x, f0.y, f0.z, f0.w, f1.x, f1.y, f1.z, f1.w};
    const float* sc = which ? g_scale2 : g_scale1;
    const float* sh = which ? g_shift2 : g_shift1;
    __half t0[8], t1[8];
#pragma unroll
    for (int j = 0; j < 8; j++) {
        float t = v[j] * sc[d0 + j] + sh[d0 + j];
        if (which == 0) t = fmaxf(t, 0.f);
        split2(t, t0[j], t1[j]);
    }
    __half* out = which ? g_A3p : g_A2p;
    size_t blk = ((size_t)(mt * 16 + kc)) * 32768;
    int off = rr * 64 + ((c * 8) ^ ((rr & 7) << 3));
    *(uint4*)&out[blk + off]         = *(uint4*)t0;
    *(uint4*)&out[blk + 16384 + off] = *(uint4*)t1;
}

__global__ void bn_stage1(int which) {
    const float* h = which ? g_h2 : g_h;
    int d = blockIdx.y * 128 + threadIdx.x;
    int s = blockIdx.x;
    float sum = 0.f, sq = 0.f;
    int m0 = s * 256, m1 = m0 + 256; if (m1 > M_TOT) m1 = M_TOT;
    for (int m = m0; m < m1; m++) {
        float v = h[(size_t)m * D_DIM + d];
        sum += v; sq += v * v;
    }
    g_part[s * D_DIM + d] = sum;
    g_part[64 * D_DIM + s * D_DIM + d] = sq;
}

__global__ void bn_stage2(const float* __restrict__ gam, const float* __restrict__ bet, int which) {
    int d = blockIdx.x * 256 + threadIdx.x;
    float sum = 0.f, sq = 0.f;
    for (int s = 0; s < 64; s++) {
        sum += g_part[s * D_DIM + d];
        sq  += g_part[64 * D_DIM + s * D_DIM + d];
    }
    float mean = sum / (float)M_TOT;
    float var  = sq / (float)M_TOT - mean * mean;
    float sc = gam[d] * rsqrtf(var + BN_EPS);
    float sh = bet[d] - mean * sc;
    if (which == 0) { g_scale1[d] = sc; g_shift1[d] = sh; }
    else            { g_scale2[d] = sc; g_shift2[d] = sh; }
}

__global__ void e2_kernel(const float* __restrict__ cb) {
    int k = blockIdx.x;
    float s = 0.f;
    for (int d = threadIdx.x; d < D_DIM; d += 128) {
        float v = cb[(size_t)k * D_DIM + d];
        s += v * v;
    }
    __shared__ float red[128];
    red[threadIdx.x] = s; __syncthreads();
    for (int off = 64; off; off >>= 1) {
        if (threadIdx.x < off) red[threadIdx.x] += red[threadIdx.x + off];
        __syncthreads();
    }
    if (threadIdx.x == 0) g_e2[k] = red[0];
}

/* ---------------- fp16x2 HMMA GEMM, bulk-copy pipelined ----------------
 * mode 0: conv1 (K=4096) out g_h + b1
 * mode 1: conv2 (K=1024) out g_h2 = g_h + . + b2
 * mode 2: VQ    (K=1024) argmin(e2 - 2*dot), 4 pairs
 */
__global__ void __launch_bounds__(256)
gemm_kernel(int mode, const float* __restrict__ aux_in, int KCS,
            const __half* __restrict__ Apack, const __half* __restrict__ Bpack) {
    extern __shared__ __align__(1024) char sm[];
    uint32_t sb = s2u(sm);
    int tid = threadIdx.x, l = tid & 31, wid = tid >> 5;
    int nt = blockIdx.x, mt = blockIdx.y;
    int n0 = nt * 128, m0 = mt * 256;

    float* auxs = (float*)(sm + 16);
    const float* aux = (mode == 2) ? g_e2 : aux_in;
    if (tid < 128) auxs[tid] = aux[n0 + tid];
    if (tid == 0) { MBAR_INIT(sb + 0, 1); MBAR_INIT(sb + 8, 1); }
    __syncthreads();

    if (tid == 0) {
#pragma unroll
        for (int c0 = 0; c0 < 2; c0++) {
            uint32_t mb = sb + 8 * c0;
            uint32_t SA = sb + 1024 + c0 * STAGE_B;
            EXPECT_TX(mb, 98304u);
            BULK_G2S(SA, Apack + ((size_t)mt * KCS + c0) * 32768, 65536u, mb);
            BULK_G2S(SA + 65536, Bpack + ((size_t)nt * KCS + c0) * 16384, 32768u, mb);
        }
    }

    float acc[4][8][4];
#pragma unroll
    for (int i = 0; i < 4; i++)
#pragma unroll
        for (int j = 0; j < 8; j++)
#pragma unroll
            for (int q = 0; q < 4; q++) acc[i][j][q] = 0.f;

    uint32_t rA[4], swA[4], rB[4], swB[4];
#pragma unroll
    for (int mi = 0; mi < 4; mi++) {
        int r = (wid & 3) * 64 + mi * 16 + (l & 15);
        rA[mi] = (uint32_t)(r * 128); swA[mi] = (uint32_t)((r & 7) << 4);
    }
    uint32_t cA = (uint32_t)((l >> 4) * 16);
#pragma unroll
    for (int g = 0; g < 4; g++) {
        int n = (wid >> 2) * 64 + g * 16 + ((l >> 4) & 1) * 8 + (l & 7);
        rB[g] = (uint32_t)(n * 128); swB[g] = (uint32_t)((n & 7) << 4);
    }
    uint32_t cB = (uint32_t)(((l >> 3) & 1) * 16);

    int ph[2] = {0, 0};
    for (int kc = 0; kc < KCS; kc++) {
        int s = kc & 1;
        uint32_t mb = sb + 8 * s;
        MBAR_WAIT(mb, ph[s]); ph[s] ^= 1;
        uint32_t SA = sb + 1024 + s * STAGE_B;
        uint32_t SB = SA + 65536;
#pragma unroll
        for (int ks = 0; ks < 4; ks++) {
            uint32_t colx = (uint32_t)(ks * 32);
            uint32_t af[2][4][4], bf[2][4][4];
#pragma unroll
            for (int comp = 0; comp < 2; comp++)
#pragma unroll
                for (int mi = 0; mi < 4; mi++)
                    LDSM4(af[comp][mi], SA + comp * 32768 + rA[mi] + ((cA + colx) ^ swA[mi]));
#pragma unroll
            for (int comp = 0; comp < 2; comp++)
#pragma unroll
                for (int g = 0; g < 4; g++)
                    LDSM4(bf[comp][g], SB + comp * 16384 + rB[g] + ((cB + colx) ^ swB[g]));
#pragma unroll
            for (int mi = 0; mi < 4; mi++) {
#pragma unroll
                for (int g = 0; g < 4; g++) {
                    MMA16(acc[mi][2 * g],     af[0][mi], bf[0][g][0], bf[0][g][1]);
                    MMA16(acc[mi][2 * g + 1], af[0][mi], bf[0][g][2], bf[0][g][3]);
                    MMA16(acc[mi][2 * g],     af[0][mi], bf[1][g][0], bf[1][g][1]);
                    MMA16(acc[mi][2 * g + 1], af[0][mi], bf[1][g][2], bf[1][g][3]);
                    MMA16(acc[mi][2 * g],     af[1][mi], bf[0][g][0], bf[0][g][1]);
                    MMA16(acc[mi][2 * g + 1], af[1][mi], bf[0][g][2], bf[0][g][3]);
                    if (mode == 2) {
                        MMA16(acc[mi][2 * g],     af[1][mi], bf[1][g][0], bf[1][g][1]);
                        MMA16(acc[mi][2 * g + 1], af[1][mi], bf[1][g][2], bf[1][g][3]);
                    }
                }
            }
        }
        __syncthreads();
        if (tid == 0 && kc + 2 < KCS) {
            EXPECT_TX(mb, 98304u);
            BULK_G2S(SA, Apack + ((size_t)mt * KCS + kc + 2) * 32768, 65536u, mb);
            BULK_G2S(SB, Bpack + ((size_t)nt * KCS + kc + 2) * 16384, 32768u, mb);
        }
    }

    /* epilogue */
    int wm = (wid & 3) * 64, wn = (wid >> 2) * 64;
    if (mode == 2) {
#pragma unroll
        for (int mi = 0; mi < 4; mi++) {
#pragma unroll
            for (int h = 0; h < 2; h++) {
                int m = m0 + wm + mi * 16 + h * 8 + (l >> 2);
                float best = 3.4e38f; int bk = 0;
#pragma unroll
                for (int nj = 0; nj < 8; nj++) {
#pragma unroll
                    for (int c = 0; c < 2; c++) {
                        int lc = wn + nj * 8 + (l & 3) * 2 + c;
                        float scv = auxs[lc] - 2.f * acc[mi][nj][h * 2 + c];
                        if (scv < best) { best = scv; bk = n0 + lc; }
                    }
                }
                unsigned long long key = packkey(best, bk);
                unsigned long long o1 = __shfl_xor_sync(0xFFFFFFFFu, key, 1);
                if (o1 < key) key = o1;
                unsigned long long o2 = __shfl_xor_sync(0xFFFFFFFFu, key, 2);
                if (o2 < key) key = o2;
                if ((l & 3) == 0 && m < M_TOT) atomicMin(&g_keys[m], key);
            }
        }
    } else {
        float* dst = mode ? g_h2 : g_h;
#pragma unroll
        for (int mi = 0; mi < 4; mi++) {
#pragma unroll
            for (int h = 0; h < 2; h++) {
                int m = m0 + wm + mi * 16 + h * 8 + (l >> 2);
                if (m >= M_TOT) continue;
#pragma unroll
                for (int nj = 0; nj < 8; nj++) {
                    int lc = wn + nj * 8 + (l & 3) * 2;
                    size_t off = (size_t)m * D_DIM + n0 + lc;
                    float2 v;
                    v.x = acc[mi][nj][h * 2]     + auxs[lc];
                    v.y = acc[mi][nj][h * 2 + 1] + auxs[lc + 1];
                    if (mode == 1) {
                        float2 rr2 = *(const float2*)(g_h + off);
                        v.x += rr2.x; v.y += rr2.y;
                    }
                    *(float2*)(dst + off) = v;
                }
            }
        }
    }
}

/* ---------------- gather + loss ---------------- */
__global__ void gather_kernel(const float* __restrict__ cb, float* __restrict__ out) {
    int b = blockIdx.y;
    int l = blockIdx.x * 32 + threadIdx.x;
    int dt = threadIdx.y;
    float local = 0.f;
    if (l < L_OUT) {
        int m = b * L_OUT + l;
        int id = (int)(unsigned)(g_keys[m] & 0xFFFFFFFFULL);
        if (dt == 0) out[Q_ELEMS + m] = (float)id;
        for (int d = dt; d < D_DIM; d += 8) {
            float q = cb[(size_t)id * D_DIM + d];
            float z = g_h2[(size_t)m * D_DIM + d] * g_scale2[d] + g_shift2[d];
            out[(size_t)b * (D_DIM * L_OUT) + (size_t)d * L_OUT + l] = q;
            float diff = z - q;
            local += diff * diff;
        }
    }
    __shared__ double red[256];
    int t = threadIdx.y * 32 + threadIdx.x;
    red[t] = (double)local;
    __syncthreads();
    for (int off = 128; off; off >>= 1) {
        if (t < off) red[t] += red[t + off];
        __syncthreads();
    }
    if (t == 0) atomicAdd(&g_loss, red[0]);
}

__global__ void finalize_kernel(float* __restrict__ out) {
    if (threadIdx.x == 0 && blockIdx.x == 0) {
        float loss = (float)(g_loss / (double)Q_ELEMS);
        out[Q_ELEMS + M_TOT]     = loss;
        out[Q_ELEMS + M_TOT + 1] = loss;
    }
}

/* ---------------- launch ---------------- */
extern "C" void kernel_launch(void* const* d_in, const int* in_sizes, int n_in,
                              void* d_out, int out_size) {
    const float* x   = (const float*)d_in[0];
    const float* w1  = (const float*)d_in[1];
    const float* b1  = (const float*)d_in[2];
    const float* g1  = (const float*)d_in[3];
    const float* be1 = (const float*)d_in[4];
    const float* w2  = (const float*)d_in[5];
    const float* b2  = (const float*)d_in[6];
    const float* g2  = (const float*)d_in[7];
    const float* be2 = (const float*)d_in[8];
    const float* cb  = (const float*)d_in[9];
    float* out = (float*)d_out;

    cudaFuncSetAttribute(gemm_kernel, cudaFuncAttributeMaxDynamicSharedMemorySize, SMEM_GEMM);

    __half *w1p, *w2p, *cbp, *axp, *a2p, *a3p;
    cudaGetSymbolAddress((void**)&w1p, g_W1p);
    cudaGetSymbolAddress((void**)&w2p, g_W2p);
    cudaGetSymbolAddress((void**)&cbp, g_CBp);
    cudaGetSymbolAddress((void**)&axp, g_Ax);
    cudaGetSymbolAddress((void**)&a2p, g_A2p);
    cudaGetSymbolAddress((void**)&a3p, g_A3p);

    init_kernel<<<64, 256>>>();
    pack_w<<<2048, 256>>>(w1, K_C1, w1p, D_DIM * K_C1 / 8);
    pack_w<<<512,  256>>>(w2, D_DIM, w2p, D_DIM * D_DIM / 8);
    pack_w<<<1024, 256>>>(cb, D_DIM, cbp, K_CB * D_DIM / 8);
    pack_x<<<32768, 256>>>(x);

    gemm_kernel<<<dim3(8, 64), 256, SMEM_GEMM>>>(0, b1, 64, axp, w1p);
    bn_stage1<<<dim3(64, 8), 128>>>(0);
    bn_stage2<<<4, 256>>>(g1, be1, 0);
    pack_bn<<<8192, 256>>>(0);

    gemm_kernel<<<dim3(8, 64), 256, SMEM_GEMM>>>(1, b2, 16, a2p, w2p);
    bn_stage1<<<dim3(64, 8), 128>>>(1);
    bn_stage2<<<4, 256>>>(g2, be2, 1);
    pack_bn<<<8192, 256>>>(1);

    e2_kernel<<<K_CB, 128>>>(cb);
    gemm_kernel<<<dim3(16, 64), 256, SMEM_GEMM>>>(2, nullptr, 16, a3p, cbp);

    gather_kernel<<<dim3(16, B_SZ), dim3(32, 8)>>>(cb, out);
    finalize_kernel<<<1, 32>>>(out);
}